// round 6
// baseline (speedup 1.0000x reference)
#include <cuda_runtime.h>
#include <cuda_bf16.h>

// Problem constants: B=512, S=32768, alpha=0.1, beta=0.9
#define B_CONST 512
#define S_CONST 32768

// log(0.1), log(0.9). Note log(1-alpha)=log(beta), log(1-beta)=log(alpha).
#define LOG_A   (-2.3025850929940457f)   // log(0.1)
#define LOG_1A  (-0.10536051565782628f)  // log(0.9)
#define LOG_B   (-0.10536051565782628f)  // log(0.9)
#define LOG_1B  (-2.3025850929940457f)   // log(0.1)

constexpr int THREADS = 256;
constexpr int IT      = 8;                  // s-values per thread
constexpr int CHUNK   = THREADS * IT;       // 2048 s per tile
constexpr int BPR     = S_CONST / CHUNK;    // 16 tiles per row
constexpr int NTILES  = B_CONST * BPR;      // 8192 tiles
constexpr int GRID    = 148 * 8;            // persistent: 1184 blocks (1 wave)

__device__ float        g_partials[GRID];
__device__ unsigned int g_count;            // zero-init; last block resets

__global__ __launch_bounds__(THREADS)
void ekl_kernel(const float* __restrict__ post,
                const int* __restrict__ length,
                float* __restrict__ out)
{
    float sum = 0.0f;

    // Persistent grid-stride over tiles: balances masked/unmasked work.
    for (int t = blockIdx.x; t < NTILES; t += GRID) {
        const int b   = t / BPR;
        const int c   = t % BPR;
        const int len = length[b];      // 1 <= len <= S (int32; L2-resident)
        const int s0  = c * CHUNK;

        if (s0 >= len) continue;        // fully masked tile

        const float2* row = reinterpret_cast<const float2*>(post)
                            + (size_t)b * S_CONST;
        const int sbase = s0 + threadIdx.x * IT;
        if (sbase >= len) continue;

        // 4 consecutive float4 loads (64B/thread, 16B-aligned).
        float c0[IT], c1[IT];
        const float4* v = reinterpret_cast<const float4*>(row + sbase);
        #pragma unroll
        for (int i = 0; i < IT / 2; ++i) {
            float4 q = v[i];
            c0[2*i]   = q.x; c1[2*i]   = q.y;
            c0[2*i+1] = q.z; c1[2*i+1] = q.w;
        }

        float pp0, pp1;
        if (sbase > 0) {
            float2 pv = row[sbase - 1];
            pp0 = pv.x; pp1 = pv.y;
        } else {
            // first-term contribution at s = 0 (len >= 1 always)
            float l0 = __logf(c0[0]);
            float l1 = __logf(c1[0]);
            sum += c1[0] * (l1 - LOG_A) + c0[0] * (l0 - LOG_1A);
            pp0 = 0.0f; pp1 = 0.0f;     // unused (s>=1 guard below)
        }

        #pragma unroll
        for (int i = 0; i < IT; ++i) {
            const int s = sbase + i;
            if (s >= 1 && s < len) {
                float q0 = c0[i], q1 = c1[i];
                float l0 = __logf(q0);
                float l1 = __logf(q1);
                float t1 = q1 * (l1 - LOG_B)  + q0 * (l0 - LOG_1B);
                float t2 = q1 * (l1 - LOG_1B) + q0 * (l0 - LOG_B);
                sum += pp1 * t1 + pp0 * t2;
            }
            pp0 = c0[i]; pp1 = c1[i];
        }
    }

    // Deterministic block reduction: warp shuffle tree + smem
    #pragma unroll
    for (int off = 16; off > 0; off >>= 1)
        sum += __shfl_down_sync(0xffffffffu, sum, off);

    __shared__ float wsum[THREADS / 32];
    const int lane = threadIdx.x & 31;
    const int wid  = threadIdx.x >> 5;
    if (lane == 0) wsum[wid] = sum;
    __syncthreads();

    if (wid == 0) {
        float v = (lane < THREADS / 32) ? wsum[lane] : 0.0f;
        #pragma unroll
        for (int off = 4; off > 0; off >>= 1)
            v += __shfl_down_sync(0xffffffffu, v, off);
        if (lane == 0) g_partials[blockIdx.x] = v;
    }

    // Last-block-wins final reduction (single launch, graph-replayable).
    __shared__ bool is_last;
    if (threadIdx.x == 0) {
        __threadfence();
        unsigned int c = atomicAdd(&g_count, 1u);
        is_last = (c == GRID - 1);
    }
    __syncthreads();

    if (is_last) {
        __threadfence();
        // 1184 partials, L2-resident. Fixed strided order -> deterministic.
        float s = 0.0f;
        for (int i = threadIdx.x; i < GRID; i += THREADS)
            s += g_partials[i];

        #pragma unroll
        for (int off = 16; off > 0; off >>= 1)
            s += __shfl_down_sync(0xffffffffu, s, off);

        if (lane == 0) wsum[wid] = s;
        __syncthreads();

        if (wid == 0) {
            float v = (lane < THREADS / 32) ? wsum[lane] : 0.0f;
            #pragma unroll
            for (int off = 4; off > 0; off >>= 1)
                v += __shfl_down_sync(0xffffffffu, v, off);
            if (lane == 0) {
                out[0]  = v / (float)B_CONST;
                g_count = 0;            // reset for next graph replay
            }
        }
    }
}

extern "C" void kernel_launch(void* const* d_in, const int* in_sizes, int n_in,
                              void* d_out, int out_size)
{
    const float* post = (const float*)d_in[0];   // (B, S, 2) f32 interleaved
    const int*   len  = (const int*)d_in[1];     // (B,) int32 on device
    float*       out  = (float*)d_out;           // scalar f32

    ekl_kernel<<<GRID, THREADS>>>(post, len, out);
}

// round 7
// speedup vs baseline: 1.1581x; 1.1581x over previous
#include <cuda_runtime.h>
#include <cuda_bf16.h>

// Problem constants: B=512, S=32768, alpha=0.1, beta=0.9
#define B_CONST 512
#define S_CONST 32768

// log(0.1), log(0.9). Note log(1-alpha)=log(beta), log(1-beta)=log(alpha).
#define LOG_A   (-2.3025850929940457f)   // log(0.1)
#define LOG_1A  (-0.10536051565782628f)  // log(0.9)
#define LOG_B   (-0.10536051565782628f)  // log(0.9)
#define LOG_1B  (-2.3025850929940457f)   // log(0.1)

constexpr int THREADS = 256;
constexpr int IT      = 8;                  // s-values per thread
constexpr int CHUNK   = THREADS * IT;       // 2048 s per block
constexpr int BPR     = S_CONST / CHUNK;    // 16 blocks per row
constexpr int GRID    = B_CONST * BPR;      // 8192 blocks

__device__ float g_partials[GRID];

// KL transition term: prev=(pp0,pp1), curr=(q0,q1)
__device__ __forceinline__ float div_term(float pp0, float pp1,
                                          float q0, float q1)
{
    float l0 = __logf(q0);
    float l1 = __logf(q1);
    float t1 = q1 * (l1 - LOG_B)  + q0 * (l0 - LOG_1B);
    float t2 = q1 * (l1 - LOG_1B) + q0 * (l0 - LOG_B);
    return pp1 * t1 + pp0 * t2;
}

__global__ __launch_bounds__(THREADS)
void ekl_main_kernel(const float* __restrict__ post,
                     const int* __restrict__ length)
{
    const int bid = blockIdx.x;
    const int b   = bid / BPR;
    const int c   = bid % BPR;
    const int len = length[b];        // 1 <= len <= S (int32)
    const int s0  = c * CHUNK;
    const int tid = threadIdx.x;

    // Slot i holds thread i's last (p0,p1). Slot THREADS = block-boundary
    // value (row[s0-1]) consumed by thread 0.
    __shared__ float2 lastpair[THREADS + 1];

    float sum = 0.0f;

    float c0[IT], c1[IT];
    bool active = false;
    int  sbase  = 0;

    if (s0 < len) {
        const float2* row = reinterpret_cast<const float2*>(post)
                            + (size_t)b * S_CONST;
        sbase = s0 + tid * IT;

        if (sbase < len) {
            active = true;
            // 4 consecutive float4 loads (64B/thread, 16B-aligned).
            const float4* v = reinterpret_cast<const float4*>(row + sbase);
            #pragma unroll
            for (int i = 0; i < IT / 2; ++i) {
                float4 q = v[i];
                c0[2*i]   = q.x; c1[2*i]   = q.y;
                c0[2*i+1] = q.z; c1[2*i+1] = q.w;
            }
            // Publish my last pair for thread tid+1.
            lastpair[tid] = make_float2(c0[IT-1], c1[IT-1]);
        }

        // Block-boundary predecessor: one 8B load per block.
        if (tid == 0 && s0 > 0)
            lastpair[THREADS] = row[s0 - 1];
    }
    __syncthreads();

    if (active) {
        float pp0, pp1;
        bool  have_prev = true;
        if (tid > 0) {
            float2 pv = lastpair[tid - 1];
            pp0 = pv.x; pp1 = pv.y;
        } else if (s0 > 0) {
            float2 pv = lastpair[THREADS];
            pp0 = pv.x; pp1 = pv.y;
        } else {
            // s == 0: first-term contribution (len >= 1 always)
            float l0 = __logf(c0[0]);
            float l1 = __logf(c1[0]);
            sum += c1[0] * (l1 - LOG_A) + c0[0] * (l0 - LOG_1A);
            pp0 = 0.0f; pp1 = 0.0f;
            have_prev = false;
        }

        if (have_prev && sbase + IT <= len) {
            // Fast path: all IT transitions valid, no per-element checks.
            #pragma unroll
            for (int i = 0; i < IT; ++i) {
                sum += div_term(pp0, pp1, c0[i], c1[i]);
                pp0 = c0[i]; pp1 = c1[i];
            }
        } else {
            // Slow path: chunk head (s==0) or masked tail.
            #pragma unroll
            for (int i = 0; i < IT; ++i) {
                const int s = sbase + i;
                if (s >= 1 && s < len)
                    sum += div_term(pp0, pp1, c0[i], c1[i]);
                pp0 = c0[i]; pp1 = c1[i];
            }
        }
    }

    // Deterministic block reduction: warp shuffle tree + smem
    #pragma unroll
    for (int off = 16; off > 0; off >>= 1)
        sum += __shfl_down_sync(0xffffffffu, sum, off);

    __shared__ float wsum[THREADS / 32];
    const int lane = tid & 31;
    const int wid  = tid >> 5;
    if (lane == 0) wsum[wid] = sum;
    __syncthreads();

    if (wid == 0) {
        float v = (lane < THREADS / 32) ? wsum[lane] : 0.0f;
        #pragma unroll
        for (int off = 4; off > 0; off >>= 1)
            v += __shfl_down_sync(0xffffffffu, v, off);
        if (lane == 0) g_partials[bid] = v;
    }
}

// Final reduction: 1024 threads, each loads 2 float4 (coalesced, MLP=2).
__global__ __launch_bounds__(1024)
void ekl_final_kernel(float* __restrict__ out)
{
    const float4* p4 = reinterpret_cast<const float4*>(g_partials);
    // 8192 floats = 2048 float4; 1024 threads * 2 each. Fixed order.
    float4 a = p4[threadIdx.x];
    float4 b = p4[threadIdx.x + 1024];
    float s = (a.x + a.y) + (a.z + a.w) + (b.x + b.y) + (b.z + b.w);

    #pragma unroll
    for (int off = 16; off > 0; off >>= 1)
        s += __shfl_down_sync(0xffffffffu, s, off);

    __shared__ float wsum[32];
    const int lane = threadIdx.x & 31;
    const int wid  = threadIdx.x >> 5;
    if (lane == 0) wsum[wid] = s;
    __syncthreads();

    if (wid == 0) {
        float v = wsum[lane];   // exactly 32 warps
        #pragma unroll
        for (int off = 16; off > 0; off >>= 1)
            v += __shfl_down_sync(0xffffffffu, v, off);
        if (lane == 0) out[0] = v / (float)B_CONST;
    }
}

extern "C" void kernel_launch(void* const* d_in, const int* in_sizes, int n_in,
                              void* d_out, int out_size)
{
    const float* post = (const float*)d_in[0];   // (B, S, 2) f32 interleaved
    const int*   len  = (const int*)d_in[1];     // (B,) int32 on device
    float*       out  = (float*)d_out;           // scalar f32

    ekl_main_kernel<<<GRID, THREADS>>>(post, len);
    ekl_final_kernel<<<1, 1024>>>(out);
}

// round 8
// speedup vs baseline: 1.1723x; 1.0122x over previous
#include <cuda_runtime.h>
#include <cuda_bf16.h>

// Problem constants: B=512, S=32768, alpha=0.1, beta=0.9
#define B_CONST 512
#define S_CONST 32768

// log(0.1), log(0.9). Note log(1-alpha)=log(beta), log(1-beta)=log(alpha).
#define LOG_A   (-2.3025850929940457f)   // log(0.1)
#define LOG_1A  (-0.10536051565782628f)  // log(0.9)
#define LOG_B   (-0.10536051565782628f)  // log(0.9)
#define LOG_1B  (-2.3025850929940457f)   // log(0.1)

constexpr int THREADS = 256;
constexpr int IT      = 8;                  // s-values per thread
constexpr int CHUNK   = THREADS * IT;       // 2048 s per block
constexpr int BPR     = S_CONST / CHUNK;    // 16 blocks per row
constexpr int GRID    = B_CONST * BPR;      // 8192 blocks

__device__ float        g_acc;              // zero-init; last block resets
__device__ unsigned int g_count;            // zero-init; last block resets

__global__ __launch_bounds__(THREADS)
void ekl_kernel(const float* __restrict__ post,
                const int* __restrict__ length,
                float* __restrict__ out)
{
    const int bid = blockIdx.x;
    const int b   = bid / BPR;
    const int c   = bid % BPR;
    const int len = length[b];        // 1 <= len <= S (int32)
    const int s0  = c * CHUNK;

    float sum = 0.0f;

    // ---- main body: identical to the proven-fastest R2 shape ----
    if (s0 < len) {
        const float2* row = reinterpret_cast<const float2*>(post)
                            + (size_t)b * S_CONST;
        const int sbase = s0 + threadIdx.x * IT;

        if (sbase < len) {
            // 4 consecutive float4 loads (64B/thread, 16B-aligned).
            float c0[IT], c1[IT];
            const float4* v = reinterpret_cast<const float4*>(row + sbase);
            #pragma unroll
            for (int i = 0; i < IT / 2; ++i) {
                float4 q = v[i];
                c0[2*i]   = q.x; c1[2*i]   = q.y;
                c0[2*i+1] = q.z; c1[2*i+1] = q.w;
            }

            float pp0, pp1;
            if (sbase > 0) {
                float2 pv = row[sbase - 1];
                pp0 = pv.x; pp1 = pv.y;
            } else {
                // first-term contribution at s = 0 (len >= 1 always)
                float l0 = __logf(c0[0]);
                float l1 = __logf(c1[0]);
                sum += c1[0] * (l1 - LOG_A) + c0[0] * (l0 - LOG_1A);
                pp0 = 0.0f; pp1 = 0.0f;   // unused (s>=1 guard below)
            }

            #pragma unroll
            for (int i = 0; i < IT; ++i) {
                const int s = sbase + i;
                if (s >= 1 && s < len) {
                    float q0 = c0[i], q1 = c1[i];
                    float l0 = __logf(q0);
                    float l1 = __logf(q1);
                    float t1 = q1 * (l1 - LOG_B)  + q0 * (l0 - LOG_1B);
                    float t2 = q1 * (l1 - LOG_1B) + q0 * (l0 - LOG_B);
                    sum += pp1 * t1 + pp0 * t2;
                }
                pp0 = c0[i]; pp1 = c1[i];
            }
        }
    }

    // Deterministic block reduction: warp shuffle tree + smem
    #pragma unroll
    for (int off = 16; off > 0; off >>= 1)
        sum += __shfl_down_sync(0xffffffffu, sum, off);

    __shared__ float wsum[THREADS / 32];
    const int lane = threadIdx.x & 31;
    const int wid  = threadIdx.x >> 5;
    if (lane == 0) wsum[wid] = sum;
    __syncthreads();

    // ---- fused epilogue: single f32 RED + counter; last block finishes ----
    if (wid == 0) {
        float v = (lane < THREADS / 32) ? wsum[lane] : 0.0f;
        #pragma unroll
        for (int off = 4; off > 0; off >>= 1)
            v += __shfl_down_sync(0xffffffffu, v, off);

        if (lane == 0) {
            atomicAdd(&g_acc, v);                 // single-address RED at L2
            __threadfence();                      // order acc-add before count
            unsigned int t = atomicAdd(&g_count, 1u);
            if (t == GRID - 1) {
                __threadfence();
                // atomicExch reads the completed total AND resets g_acc
                // for the next graph replay.
                float tot = atomicExch(&g_acc, 0.0f);
                out[0]  = tot / (float)B_CONST;
                g_count = 0;                      // reset for next replay
            }
        }
    }
}

extern "C" void kernel_launch(void* const* d_in, const int* in_sizes, int n_in,
                              void* d_out, int out_size)
{
    const float* post = (const float*)d_in[0];   // (B, S, 2) f32 interleaved
    const int*   len  = (const int*)d_in[1];     // (B,) int32 on device
    float*       out  = (float*)d_out;           // scalar f32

    ekl_kernel<<<GRID, THREADS>>>(post, len, out);
}

// round 9
// speedup vs baseline: 1.2990x; 1.1081x over previous
#include <cuda_runtime.h>
#include <cuda_bf16.h>

// Problem constants: B=512, S=32768, alpha=0.1, beta=0.9
#define B_CONST 512
#define S_CONST 32768

// log(0.1), log(0.9). Note log(1-alpha)=log(beta), log(1-beta)=log(alpha).
#define LOG_A   (-2.3025850929940457f)   // log(0.1)
#define LOG_1A  (-0.10536051565782628f)  // log(0.9)
#define LOG_B   (-0.10536051565782628f)  // log(0.9)
#define LOG_1B  (-2.3025850929940457f)   // log(0.1)

constexpr int THREADS = 256;              // 8 warps
constexpr int WSEG    = 256;              // s-values per warp (4 iters x 64)
constexpr int CHUNK   = (THREADS / 32) * WSEG;   // 2048 s per block
constexpr int BPR     = S_CONST / CHUNK;  // 16 blocks per row
constexpr int GRID    = B_CONST * BPR;    // 8192 blocks
constexpr unsigned FULL = 0xffffffffu;

__device__ float g_partials[GRID];

// KL transition term: prev=(pp0,pp1), curr=(q0,q1)
__device__ __forceinline__ float div_term(float pp0, float pp1,
                                          float q0, float q1)
{
    float l0 = __logf(q0);
    float l1 = __logf(q1);
    float t1 = q1 * (l1 - LOG_B)  + q0 * (l0 - LOG_1B);
    float t2 = q1 * (l1 - LOG_1B) + q0 * (l0 - LOG_B);
    return pp1 * t1 + pp0 * t2;
}

__global__ __launch_bounds__(THREADS)
void ekl_main_kernel(const float* __restrict__ post,
                     const int* __restrict__ length)
{
    const int bid  = blockIdx.x;
    const int b    = bid / BPR;
    const int c    = bid % BPR;
    const int len  = length[b];       // 1 <= len <= S (int32)
    const int s0   = c * CHUNK;
    const int lane = threadIdx.x & 31;
    const int warp = threadIdx.x >> 5;

    float sum = 0.0f;

    // Warp-uniform segment: s in [segbase, segbase + WSEG)
    const int segbase = s0 + warp * WSEG;

    if (segbase < len) {
        const float2* row  = reinterpret_cast<const float2*>(post)
                             + (size_t)b * S_CONST;
        const float4* rowq = reinterpret_cast<const float4*>(row);
        const int qbase = (segbase >> 1);   // quad index of segment start

        // Coalesced loads: iteration i covers s in [segbase+i*64, +64),
        // lane l holds the quad (pairs at s = segbase+i*64+2l, +2l+1).
        // Lanes are CONTIGUOUS float4s -> 4 L1 wavefronts per LDG.128.
        // All loads stay inside the row (tiles never cross row end).
        float4 V[4];
        #pragma unroll
        for (int i = 0; i < 4; ++i)
            if (segbase + i * 64 < len)
                V[i] = rowq[qbase + i * 32 + lane];

        // Cross-warp-boundary carry: pair at s = segbase-1 (lane 0 only).
        float cr0 = 0.0f, cr1 = 0.0f;
        if (segbase > 0 && lane == 0) {
            float2 pv = row[segbase - 1];
            cr0 = pv.x; cr1 = pv.y;
        }

        #pragma unroll
        for (int i = 0; i < 4; ++i) {
            if (segbase + i * 64 >= len) break;   // warp-uniform

            float c0a = V[i].x, c1a = V[i].y;     // pair at s = sidx
            float c0b = V[i].z, c1b = V[i].w;     // pair at s = sidx+1

            // prev pair for sidx: lane l-1's (c0b,c1b); lane 0 takes carry.
            float pv0 = __shfl_up_sync(FULL, c0b, 1);
            float pv1 = __shfl_up_sync(FULL, c1b, 1);
            if (lane == 0) { pv0 = cr0; pv1 = cr1; }

            const int sidx = segbase + i * 64 + 2 * lane;

            if (sidx == 0) {
                // first-term contribution at s = 0 (len >= 1 always)
                float l0 = __logf(c0a);
                float l1 = __logf(c1a);
                sum += c1a * (l1 - LOG_A) + c0a * (l0 - LOG_1A);
            } else if (sidx < len) {
                sum += div_term(pv0, pv1, c0a, c1a);
            }
            if (sidx + 1 < len)
                sum += div_term(c0a, c1a, c0b, c1b);

            // carry for next iteration = this iteration's lane-31 last pair
            cr0 = __shfl_sync(FULL, c0b, 31);
            cr1 = __shfl_sync(FULL, c1b, 31);
        }
    }

    // Deterministic block reduction: warp shuffle tree + smem
    #pragma unroll
    for (int off = 16; off > 0; off >>= 1)
        sum += __shfl_down_sync(FULL, sum, off);

    __shared__ float wsum[THREADS / 32];
    if (lane == 0) wsum[warp] = sum;
    __syncthreads();

    if (warp == 0) {
        float v = (lane < THREADS / 32) ? wsum[lane] : 0.0f;
        #pragma unroll
        for (int off = 4; off > 0; off >>= 1)
            v += __shfl_down_sync(FULL, v, off);
        if (lane == 0) g_partials[bid] = v;
    }
}

// Final reduction: 1024 threads, each loads 2 float4 (coalesced, MLP=2).
__global__ __launch_bounds__(1024)
void ekl_final_kernel(float* __restrict__ out)
{
    const float4* p4 = reinterpret_cast<const float4*>(g_partials);
    // 8192 floats = 2048 float4; 1024 threads * 2 each. Fixed order.
    float4 a = p4[threadIdx.x];
    float4 b = p4[threadIdx.x + 1024];
    float s = (a.x + a.y) + (a.z + a.w) + (b.x + b.y) + (b.z + b.w);

    #pragma unroll
    for (int off = 16; off > 0; off >>= 1)
        s += __shfl_down_sync(0xffffffffu, s, off);

    __shared__ float wsum[32];
    const int lane = threadIdx.x & 31;
    const int wid  = threadIdx.x >> 5;
    if (lane == 0) wsum[wid] = s;
    __syncthreads();

    if (wid == 0) {
        float v = wsum[lane];   // exactly 32 warps
        #pragma unroll
        for (int off = 16; off > 0; off >>= 1)
            v += __shfl_down_sync(0xffffffffu, v, off);
        if (lane == 0) out[0] = v / (float)B_CONST;
    }
}

extern "C" void kernel_launch(void* const* d_in, const int* in_sizes, int n_in,
                              void* d_out, int out_size)
{
    const float* post = (const float*)d_in[0];   // (B, S, 2) f32 interleaved
    const int*   len  = (const int*)d_in[1];     // (B,) int32 on device
    float*       out  = (float*)d_out;           // scalar f32

    ekl_main_kernel<<<GRID, THREADS>>>(post, len);
    ekl_final_kernel<<<1, 1024>>>(out);
}